// round 15
// baseline (speedup 1.0000x reference)
#include <cuda_runtime.h>
#include <cstdint>

// ---------------------------------------------------------------------------
// Problem constants
// ---------------------------------------------------------------------------
#define BATCH  256
#define SEQ    2048
#define IND    4
#define HID    256

// 16 clusters x 8 CTAs = 128 CTAs. Cluster placement constraint is per-cluster
// same-die (74 SMs/die -> 9+7 clusters pack), so one wave is expected.
// Cluster owns MG=16 batch rows (ONE group). CTA rank r owns h-indices
// [32r,32r+32) -> 128 W_hh rows as tf32 register fragments.
// 8 warps: warp = (kg in {0,1}, nq in {0..3}).
// Exchange: STG slice -> L2, ONE cp.async.bulk multicast::cluster per CTA per
// step delivers into all 8 CTAs' A buffers. A TRIPLE-buffered; the full-barrier
// chain replaces any consume barrier (R9 protocol, group dimension removed).
#define CLUSTER 8
#define NCLUST  16
#define MG      16
#define JPC     32
#define THREADS 256

#define AS_KSTR 20                      // 16 rows + 4 pad words
#define AS_BUF  (HID * AS_KSTR)         // 5120 floats per buffer
#define ZS_RSTR 132
#define ZS_BUF  (MG * ZS_RSTR)          // 2112 floats per k-group
#define SLICE_W (JPC * AS_KSTR)         // 640 words per CTA slice
#define SLICE_B (SLICE_W * 4)           // 2560 bytes
#define FULL_TX (CLUSTER * SLICE_B)     // 20480 bytes (8 multicast slices)

// dynamic smem layout (float offsets); mbarriers full[ph] in first 16 words
#define OFF_AS    16
#define OFF_ZS    (OFF_AS + 3 * AS_BUF)      // 15376
#define OFF_WIH   (OFF_ZS + 2 * ZS_BUF)      // 19600
#define OFF_BIAS  (OFF_WIH + 512)            // 20112
#define OFF_XS    (OFF_BIAS + 128)           // 20240
#define SMEM_FLOATS (OFF_XS + 2 * MG * 4)    // 20368
#define SMEM_BYTES  (SMEM_FLOATS * 4)        // 81472

// ---------------------------------------------------------------------------
// Global scratch
// ---------------------------------------------------------------------------
__device__ float g_hx[NCLUST][3][CLUSTER * SLICE_W];  // [clust][phase]
__device__ float g_hfin[BATCH * HID];
__device__ float g_feat[2 * BATCH];

// ---------------------------------------------------------------------------
// helpers
// ---------------------------------------------------------------------------
__device__ __forceinline__ uint32_t tf32u(float v) {
    uint32_t r; asm("cvt.rna.tf32.f32 %0, %1;" : "=r"(r) : "f"(v)); return r;
}
__device__ __forceinline__ float rtf32(float v) { return __uint_as_float(tf32u(v)); }
__device__ __forceinline__ float tanh_a(float x) {
    float y; asm("tanh.approx.f32 %0, %1;" : "=f"(y) : "f"(x)); return y;
}
__device__ __forceinline__ float sig_t(float x) { return 0.5f * tanh_a(0.5f * x) + 0.5f; }
__device__ __forceinline__ float fast_sigmoid(float x) {
    float e = __expf(-x); return __fdividef(1.0f, 1.0f + e);
}
__device__ __forceinline__ float dot4(float4 a, float4 b) {
    return a.x * b.x + a.y * b.y + a.z * b.z + a.w * b.w;
}
__device__ __forceinline__ uint32_t smem_u32(const void* p) {
    uint32_t a;
    asm("{ .reg .u64 t; cvta.to.shared.u64 t, %1; cvt.u32.u64 %0, t; }" : "=r"(a) : "l"(p));
    return a;
}
__device__ __forceinline__ uint32_t cta_rank() {
    uint32_t r; asm("mov.u32 %0, %%cluster_ctarank;" : "=r"(r)); return r;
}
__device__ __forceinline__ void mbar_init(uint32_t mbar, uint32_t cnt) {
    asm volatile("mbarrier.init.shared.b64 [%0], %1;" :: "r"(mbar), "r"(cnt) : "memory");
}
__device__ __forceinline__ void mbar_expect(uint32_t mbar, uint32_t bytes) {
    asm volatile("mbarrier.arrive.expect_tx.shared.b64 _, [%0], %1;"
                 :: "r"(mbar), "r"(bytes) : "memory");
}
__device__ __forceinline__ void mbar_wait(uint32_t mbar, uint32_t parity) {
    asm volatile(
        "{\n\t.reg .pred P;\n\t"
        "W_%=:\n\t"
        "mbarrier.try_wait.parity.acquire.cta.shared::cta.b64 P, [%0], %1, 0x989680;\n\t"
        "@P bra D_%=;\n\t"
        "bra W_%=;\n\t"
        "D_%=:\n\t}"
        :: "r"(mbar), "r"(parity) : "memory");
}
__device__ __forceinline__ void bulk_mc_g2s(uint32_t dst, const void* src,
                                            uint32_t bytes, uint32_t mbar,
                                            uint16_t mask) {
    asm volatile("cp.async.bulk.shared::cluster.global."
                 "mbarrier::complete_tx::bytes.multicast::cluster "
                 "[%0], [%1], %2, [%3], %4;"
                 :: "r"(dst), "l"(src), "r"(bytes), "r"(mbar), "h"(mask) : "memory");
}

// ---------------------------------------------------------------------------
// Kernel 1: conv_feat + kernel_sim
// ---------------------------------------------------------------------------
__global__ void feat_kernel(const float* __restrict__ x,
                            const float* __restrict__ conv_w,
                            const float* __restrict__ conv_b) {
    __shared__ float r0[256];
    __shared__ float r1[256];
    int b = blockIdx.x, tid = threadIdx.x;
    float4 cw = *(const float4*)conv_w;
    float cb = conv_b[0];
    const float4* xr = (const float4*)(x + (size_t)b * SEQ * IND);
    float ssig = 0.f, ssq = 0.f;
    for (int s = tid; s < SEQ; s += 256) {
        float4 v = xr[s];
        float d = v.x * cw.x + v.y * cw.y + v.z * cw.z + v.w * cw.w + cb;
        ssig += fast_sigmoid(d);
        ssq  += v.x * v.x + v.y * v.y + v.z * v.z + v.w * v.w;
    }
    r0[tid] = ssig; r1[tid] = ssq;
    __syncthreads();
    for (int o = 128; o > 0; o >>= 1) {
        if (tid < o) { r0[tid] += r0[tid + o]; r1[tid] += r1[tid + o]; }
        __syncthreads();
    }
    if (tid == 0) {
        g_feat[b]         = r0[0] * (1.0f / SEQ);
        g_feat[BATCH + b] = __expf(-r1[0]);
    }
}

// ---------------------------------------------------------------------------
// Kernel 2: LSTM recurrence; 16 clusters, MG=16, R9 exchange protocol
// ---------------------------------------------------------------------------
__global__ void __cluster_dims__(CLUSTER, 1, 1) __launch_bounds__(THREADS, 1)
lstm_kernel(const float* __restrict__ x,
            const float* __restrict__ W_ih,
            const float* __restrict__ W_hh,
            const float* __restrict__ b_ih,
            const float* __restrict__ b_hh) {
    extern __shared__ float sm[];
    float* As    = sm + OFF_AS;
    float* Zs    = sm + OFF_ZS;
    float* WihS  = sm + OFF_WIH;
    float* BiasS = sm + OFF_BIAS;
    float* Xs    = sm + OFF_XS;

    const uint32_t sbase = smem_u32(sm);

    const int tid   = threadIdx.x;
    const int cid   = blockIdx.x / CLUSTER;
    const uint32_t rank = cta_rank();
    const int bbase = cid * MG;
    const int j0    = (int)rank * JPC;
    const int warp  = tid >> 5, lane = tid & 31;
    const int kg    = warp >> 2, nq = warp & 3;
    const int g     = lane >> 2, tig = lane & 3;

    // ---- one-time: W_hh register fragments (tf32) ----
    uint32_t Breg[4][16][2];
    #pragma unroll
    for (int s = 0; s < 4; ++s) {
        const int nl   = nq * 32 + s * 8 + g;
        const int gate = nl >> 5, jj = nl & 31;
        const float* wrow = W_hh + (size_t)(gate * HID + j0 + jj) * HID + kg * 128;
        #pragma unroll
        for (int kt = 0; kt < 16; ++kt) {
            Breg[s][kt][0] = tf32u(wrow[kt * 8 + tig]);
            Breg[s][kt][1] = tf32u(wrow[kt * 8 + tig + 4]);
        }
    }
    if (tid < 128) {
        int gate = tid >> 5, jj = tid & 31;
        int grow = gate * HID + j0 + jj;
        BiasS[tid] = b_ih[grow] + b_hh[grow];
        WihS[tid * 4 + 0] = W_ih[grow * IND + 0];
        WihS[tid * 4 + 1] = W_ih[grow * IND + 1];
        WihS[tid * 4 + 2] = W_ih[grow * IND + 2];
        WihS[tid * 4 + 3] = W_ih[grow * IND + 3];
    }
    // zero phase-0 A buffer (h_0 = 0)
    for (int i = tid; i < AS_BUF; i += THREADS) As[i] = 0.0f;
    if (tid < MG)
        *(float4*)(Xs + tid * 4) = *(const float4*)(x + (size_t)(bbase + tid) * SEQ * IND);
    if (tid == 0) {
        #pragma unroll
        for (int i = 0; i < 3; ++i) {           // full[ph]
            mbar_init(sbase + i * 8, 1);
            mbar_expect(sbase + i * 8, FULL_TX);
        }
        asm volatile("fence.mbarrier_init.release.cluster;" ::: "memory");
    }
    __syncthreads();
    asm volatile("barrier.cluster.arrive.aligned;" ::: "memory");
    asm volatile("barrier.cluster.wait.aligned;"   ::: "memory");

    // gate-phase ownership: col jl = tid&31; thread qh = tid>>5 owns rows
    // {qh, qh+8}  (interleave positions 2qh, 2qh+1)
    const int jl = tid & 31;
    const int qh = tid >> 5;

    // hoisted loop-invariant gate weights/biases
    const float4 wiv = *(const float4*)(WihS + (jl)      * 4);
    const float4 wfv = *(const float4*)(WihS + (32 + jl) * 4);
    const float4 wgv = *(const float4*)(WihS + (64 + jl) * 4);
    const float4 wov = *(const float4*)(WihS + (96 + jl) * 4);
    const float bi = BiasS[jl], bf = BiasS[32 + jl];
    const float bg = BiasS[64 + jl], bo = BiasS[96 + jl];

    float c0s = 0.f, c1s = 0.f;
    uint32_t pf[3] = {0, 0, 0};

    int ph = 0;   // t % 3
    for (int t = 0; t < SEQ; ++t) {
        const int p   = t & 1;               // Xs parity only
        const int ph1 = (ph == 2) ? 0 : ph + 1;
        const uint32_t mbfull_p = sbase + ph * 8;
        const uint32_t mbfull_n = sbase + ph1 * 8;

        // prefetch x_{t+1}
        float4 xpre;
        const bool do_x = (tid < MG) && (t + 1 < SEQ);
        if (do_x)
            xpre = *(const float4*)(x + ((size_t)(bbase + tid) * SEQ + (t + 1)) * IND);

        // wait for A phase (t=0: locally zeroed)
        if (t > 0) {
            mbar_wait(mbfull_p, pf[ph]);
            pf[ph] ^= 1;
            if (tid == 0) mbar_expect(mbfull_p, FULL_TX);
        }

        // ---- z_partial(kg) = h @ W^T for this warp's 32 n-rows ----
        const uint32_t* Au = (const uint32_t*)(As + ph * AS_BUF);
        float acc[4][4];
        #pragma unroll
        for (int s = 0; s < 4; ++s)
            #pragma unroll
            for (int q = 0; q < 4; ++q) acc[s][q] = 0.0f;

        #pragma unroll
        for (int kt = 0; kt < 16; ++kt) {
            const int kb = kg * 128 + kt * 8 + tig;
            uint2 A0  = *(const uint2*)(Au + (size_t)kb * AS_KSTR + 2 * g);
            uint2 A0b = *(const uint2*)(Au + (size_t)(kb + 4) * AS_KSTR + 2 * g);
            #pragma unroll
            for (int s = 0; s < 4; ++s) {
                asm("mma.sync.aligned.m16n8k8.row.col.f32.tf32.tf32.f32 "
                    "{%0,%1,%2,%3},{%4,%5,%6,%7},{%8,%9},{%0,%1,%2,%3};"
                    : "+f"(acc[s][0]), "+f"(acc[s][1]), "+f"(acc[s][2]), "+f"(acc[s][3])
                    : "r"(A0.x), "r"(A0.y), "r"(A0b.x), "r"(A0b.y),
                      "r"(Breg[s][kt][0]), "r"(Breg[s][kt][1]));
            }
        }
        {
            float* Zp = Zs + kg * ZS_BUF;
            #pragma unroll
            for (int s = 0; s < 4; ++s) {
                const int n0 = nq * 32 + s * 8;
                *(float2*)(Zp + (size_t)g * ZS_RSTR + n0 + 2 * tig) =
                    make_float2(acc[s][0], acc[s][1]);
                *(float2*)(Zp + (size_t)(g + 8) * ZS_RSTR + n0 + 2 * tig) =
                    make_float2(acc[s][2], acc[s][3]);
            }
        }
        __syncthreads();

        // stash prefetched x (covered by later syncs)
        if (do_x) *(float4*)(Xs + (p ^ 1) * (MG * 4) + tid * 4) = xpre;

        // ---- gates: rows {qh, qh+8}, column j0+jl ----
        float h0, h1;
        {
            const float4 xv0 = *(const float4*)(Xs + p * (MG * 4) + qh * 4);
            const float4 xv1 = *(const float4*)(Xs + p * (MG * 4) + (qh + 8) * 4);
            const float* z0 = Zs + (size_t)qh * ZS_RSTR;        // kg 0
            const float* z1 = z0 + ZS_BUF;                      // kg 1
            const float* y0 = Zs + (size_t)(qh + 8) * ZS_RSTR;
            const float* y1 = y0 + ZS_BUF;
            float ai = z0[jl]      + z1[jl]      + bi + dot4(wiv, xv0);
            float af = z0[32 + jl] + z1[32 + jl] + bf + dot4(wfv, xv0);
            float ag = z0[64 + jl] + z1[64 + jl] + bg + dot4(wgv, xv0);
            float ao = z0[96 + jl] + z1[96 + jl] + bo + dot4(wov, xv0);
            float gi = sig_t(ai), gf = sig_t(af), go = sig_t(ao);
            float gg = tanh_a(ag);
            float cn = gf * c0s + gi * gg;
            c0s = cn;
            h0 = rtf32(go * tanh_a(cn));

            ai = y0[jl]      + y1[jl]      + bi + dot4(wiv, xv1);
            af = y0[32 + jl] + y1[32 + jl] + bf + dot4(wfv, xv1);
            ag = y0[64 + jl] + y1[64 + jl] + bg + dot4(wgv, xv1);
            ao = y0[96 + jl] + y1[96 + jl] + bo + dot4(wov, xv1);
            gi = sig_t(ai); gf = sig_t(af); go = sig_t(ao);
            gg = tanh_a(ag);
            cn = gf * c1s + gi * gg;
            c1s = cn;
            h1 = rtf32(go * tanh_a(cn));
        }

        if (t + 1 < SEQ) {
            // publish own slice to L2 staging (interleaved A layout)
            __stcg((float2*)&g_hx[cid][ph1]
                       [(size_t)rank * SLICE_W + jl * AS_KSTR + 2 * qh],
                   make_float2(h0, h1));
            __syncthreads();   // all slice STGs issued before elected fence

            // elected: ONE multicast bulk to all 8 CTAs' A[ph1].
            // Triple buffering: passing full[ph] transitively proves every
            // peer finished reading ph1 (step t-2).
            if (tid == 0) {
                asm volatile("fence.proxy.async.global;" ::: "memory");
                const uint32_t dstl =
                    sbase + (OFF_AS + ph1 * AS_BUF + j0 * AS_KSTR) * 4;
                bulk_mc_g2s(dstl, &g_hx[cid][ph1][(size_t)rank * SLICE_W],
                            SLICE_B, mbfull_n, (uint16_t)0xFF);
            }
        } else {
            g_hfin[(size_t)(bbase + qh) * HID + j0 + jl]     = h0;
            g_hfin[(size_t)(bbase + qh + 8) * HID + j0 + jl] = h1;
        }
        ph = ph1;
    }

    // no publish at t=SEQ-1 -> nothing in flight beyond barriers we consumed
    asm volatile("barrier.cluster.arrive.aligned;" ::: "memory");
    asm volatile("barrier.cluster.wait.aligned;"   ::: "memory");
}

// ---------------------------------------------------------------------------
// Kernel 3: head
// ---------------------------------------------------------------------------
__global__ void head_kernel(const float* __restrict__ fc_w,
                            const float* __restrict__ fc_b,
                            const float* __restrict__ out_w,
                            const float* __restrict__ out_b,
                            float* __restrict__ out) {
    __shared__ float hsh[HID];
    __shared__ float r0[256];
    __shared__ float r1[256];
    int b = blockIdx.x, tid = threadIdx.x;
    hsh[tid] = g_hfin[b * HID + tid];
    __syncthreads();
    float cf = g_feat[b], ks = g_feat[BATCH + b];
    const float* wr = fc_w + (size_t)tid * (HID + 2);
    float acc = fc_b[tid] + wr[0] * cf + wr[HID + 1] * ks;
    #pragma unroll 8
    for (int k = 0; k < HID; ++k) acc += wr[1 + k] * hsh[k];
    float hid = fmaxf(acc, 0.0f);
    r0[tid] = hid * out_w[tid];
    r1[tid] = hid * out_w[HID + tid];
    __syncthreads();
    for (int o = 128; o > 0; o >>= 1) {
        if (tid < o) { r0[tid] += r0[tid + o]; r1[tid] += r1[tid + o]; }
        __syncthreads();
    }
    if (tid == 0) {
        float l0 = r0[0] + out_b[0];
        float l1 = r1[0] + out_b[1];
        float m  = fmaxf(l0, l1);
        float e0 = __expf(l0 - m), e1 = __expf(l1 - m);
        float inv = __fdividef(1.0f, e0 + e1);
        out[b * 2 + 0] = e0 * inv;
        out[b * 2 + 1] = e1 * inv;
    }
}

// ---------------------------------------------------------------------------
// launch (lstm first so the fixed ncu sampling slot captures it)
// ---------------------------------------------------------------------------
extern "C" void kernel_launch(void* const* d_in, const int* in_sizes, int n_in,
                              void* d_out, int out_size) {
    const float* x      = (const float*)d_in[0];
    const float* conv_w = (const float*)d_in[1];
    const float* conv_b = (const float*)d_in[2];
    const float* W_ih   = (const float*)d_in[3];
    const float* W_hh   = (const float*)d_in[4];
    const float* b_ih   = (const float*)d_in[5];
    const float* b_hh   = (const float*)d_in[6];
    const float* fc_w   = (const float*)d_in[7];
    const float* fc_b   = (const float*)d_in[8];
    const float* out_w  = (const float*)d_in[9];
    const float* out_b  = (const float*)d_in[10];
    float* out = (float*)d_out;

    cudaFuncSetAttribute(lstm_kernel, cudaFuncAttributeMaxDynamicSharedMemorySize,
                         SMEM_BYTES);

    lstm_kernel<<<NCLUST * CLUSTER, THREADS, SMEM_BYTES>>>(x, W_ih, W_hh, b_ih, b_hh);
    feat_kernel<<<BATCH, 256>>>(x, conv_w, conv_b);
    head_kernel<<<BATCH, 256>>>(fc_w, fc_b, out_w, out_b, out);
}

// round 16
// speedup vs baseline: 1.0877x; 1.0877x over previous
#include <cuda_runtime.h>
#include <cstdint>

// ---------------------------------------------------------------------------
// Problem constants
// ---------------------------------------------------------------------------
#define BATCH  256
#define SEQ    2048
#define IND    4
#define HID    256

// 8 clusters x 8 CTAs = 64 CTAs (single wave), 512 threads (16 warps).
// Cluster owns 32 batch rows in TWO pipelined groups of 16. CTA rank r owns
// h-indices [32r,32r+32) -> 128 W_hh rows as tf32 register fragments.
// 16 warps: warp = (kg in {0..3}, nq in {0..3}) -> n-rows [32nq,32nq+32),
// k-quarter [64kg, 64kg+64). 4 warps/SMSP hide LDS/mma latency.
// Exchange (R9 protocol, unchanged): STG slice -> L2, ONE cp.async.bulk
// multicast::cluster per CTA per group into all 8 CTAs' A buffers; A is
// TRIPLE-buffered per group, full-barrier chain replaces consume barrier.
#define CLUSTER 8
#define NCLUST  8
#define MG      32
#define MGG     16
#define JPC     32
#define THREADS 512

#define AS_KSTR 20                      // 16 rows + 4 pad words
#define AS_BUF  (HID * AS_KSTR)         // 5120 floats per buffer
#define ZS_RSTR 132
#define ZS_BUF  (MGG * ZS_RSTR)         // 2112 floats per k-quarter
#define SLICE_W (JPC * AS_KSTR)         // 640 words per CTA slice
#define SLICE_B (SLICE_W * 4)           // 2560 bytes
#define FULL_TX (CLUSTER * SLICE_B)     // 20480 bytes (8 multicast slices)

// dynamic smem layout (float offsets); mbarriers full[g][ph] in first 16 words
#define OFF_AS    16
#define OFF_ZS    (OFF_AS + 6 * AS_BUF)      // 30736 (A[g][ph] = (g*3+ph)*AS_BUF)
#define OFF_WIH   (OFF_ZS + 4 * ZS_BUF)      // 39184 (Z per k-quarter)
#define OFF_BIAS  (OFF_WIH + 512)            // 39696
#define OFF_XS    (OFF_BIAS + 128)           // 39824
#define SMEM_FLOATS (OFF_XS + 2 * MG * 4)    // 40080
#define SMEM_BYTES  (SMEM_FLOATS * 4)        // 160320

// ---------------------------------------------------------------------------
// Global scratch
// ---------------------------------------------------------------------------
__device__ float g_hx[NCLUST][2][3][CLUSTER * SLICE_W];  // [clust][group][phase]
__device__ float g_hfin[BATCH * HID];
__device__ float g_feat[2 * BATCH];

// ---------------------------------------------------------------------------
// helpers
// ---------------------------------------------------------------------------
__device__ __forceinline__ uint32_t tf32u(float v) {
    uint32_t r; asm("cvt.rna.tf32.f32 %0, %1;" : "=r"(r) : "f"(v)); return r;
}
__device__ __forceinline__ float rtf32(float v) { return __uint_as_float(tf32u(v)); }
__device__ __forceinline__ float tanh_a(float x) {
    float y; asm("tanh.approx.f32 %0, %1;" : "=f"(y) : "f"(x)); return y;
}
__device__ __forceinline__ float sig_t(float x) { return 0.5f * tanh_a(0.5f * x) + 0.5f; }
__device__ __forceinline__ float fast_sigmoid(float x) {
    float e = __expf(-x); return __fdividef(1.0f, 1.0f + e);
}
__device__ __forceinline__ float dot4(float4 a, float4 b) {
    return a.x * b.x + a.y * b.y + a.z * b.z + a.w * b.w;
}
__device__ __forceinline__ uint32_t smem_u32(const void* p) {
    uint32_t a;
    asm("{ .reg .u64 t; cvta.to.shared.u64 t, %1; cvt.u32.u64 %0, t; }" : "=r"(a) : "l"(p));
    return a;
}
__device__ __forceinline__ uint32_t cta_rank() {
    uint32_t r; asm("mov.u32 %0, %%cluster_ctarank;" : "=r"(r)); return r;
}
__device__ __forceinline__ void mbar_init(uint32_t mbar, uint32_t cnt) {
    asm volatile("mbarrier.init.shared.b64 [%0], %1;" :: "r"(mbar), "r"(cnt) : "memory");
}
__device__ __forceinline__ void mbar_expect(uint32_t mbar, uint32_t bytes) {
    asm volatile("mbarrier.arrive.expect_tx.shared.b64 _, [%0], %1;"
                 :: "r"(mbar), "r"(bytes) : "memory");
}
__device__ __forceinline__ void mbar_wait(uint32_t mbar, uint32_t parity) {
    asm volatile(
        "{\n\t.reg .pred P;\n\t"
        "W_%=:\n\t"
        "mbarrier.try_wait.parity.acquire.cta.shared::cta.b64 P, [%0], %1, 0x989680;\n\t"
        "@P bra D_%=;\n\t"
        "bra W_%=;\n\t"
        "D_%=:\n\t}"
        :: "r"(mbar), "r"(parity) : "memory");
}
__device__ __forceinline__ void bulk_mc_g2s(uint32_t dst, const void* src,
                                            uint32_t bytes, uint32_t mbar,
                                            uint16_t mask) {
    asm volatile("cp.async.bulk.shared::cluster.global."
                 "mbarrier::complete_tx::bytes.multicast::cluster "
                 "[%0], [%1], %2, [%3], %4;"
                 :: "r"(dst), "l"(src), "r"(bytes), "r"(mbar), "h"(mask) : "memory");
}

// ---------------------------------------------------------------------------
// Kernel 1: conv_feat + kernel_sim
// ---------------------------------------------------------------------------
__global__ void feat_kernel(const float* __restrict__ x,
                            const float* __restrict__ conv_w,
                            const float* __restrict__ conv_b) {
    __shared__ float r0[256];
    __shared__ float r1[256];
    int b = blockIdx.x, tid = threadIdx.x;
    float4 cw = *(const float4*)conv_w;
    float cb = conv_b[0];
    const float4* xr = (const float4*)(x + (size_t)b * SEQ * IND);
    float ssig = 0.f, ssq = 0.f;
    for (int s = tid; s < SEQ; s += 256) {
        float4 v = xr[s];
        float d = v.x * cw.x + v.y * cw.y + v.z * cw.z + v.w * cw.w + cb;
        ssig += fast_sigmoid(d);
        ssq  += v.x * v.x + v.y * v.y + v.z * v.z + v.w * v.w;
    }
    r0[tid] = ssig; r1[tid] = ssq;
    __syncthreads();
    for (int o = 128; o > 0; o >>= 1) {
        if (tid < o) { r0[tid] += r0[tid + o]; r1[tid] += r1[tid + o]; }
        __syncthreads();
    }
    if (tid == 0) {
        g_feat[b]         = r0[0] * (1.0f / SEQ);
        g_feat[BATCH + b] = __expf(-r1[0]);
    }
}

// ---------------------------------------------------------------------------
// Kernel 2: LSTM recurrence; 16 warps, 4-way k-split, R9 exchange protocol
// ---------------------------------------------------------------------------
__global__ void __cluster_dims__(CLUSTER, 1, 1) __launch_bounds__(THREADS, 1)
lstm_kernel(const float* __restrict__ x,
            const float* __restrict__ W_ih,
            const float* __restrict__ W_hh,
            const float* __restrict__ b_ih,
            const float* __restrict__ b_hh) {
    extern __shared__ float sm[];
    float* As    = sm + OFF_AS;
    float* Zs    = sm + OFF_ZS;
    float* WihS  = sm + OFF_WIH;
    float* BiasS = sm + OFF_BIAS;
    float* Xs    = sm + OFF_XS;

    const uint32_t sbase = smem_u32(sm);

    const int tid   = threadIdx.x;
    const int cid   = blockIdx.x / CLUSTER;
    const uint32_t rank = cta_rank();
    const int bbase = cid * MG;
    const int j0    = (int)rank * JPC;
    const int warp  = tid >> 5, lane = tid & 31;
    const int kg    = warp >> 2, nq = warp & 3;   // k-quarter, n-block
    const int g     = lane >> 2, tig = lane & 3;

    // ---- one-time: W_hh register fragments (tf32), quarter-k ----
    uint32_t Breg[4][8][2];
    #pragma unroll
    for (int s = 0; s < 4; ++s) {
        const int nl   = nq * 32 + s * 8 + g;
        const int gate = nl >> 5, jj = nl & 31;
        const float* wrow = W_hh + (size_t)(gate * HID + j0 + jj) * HID + kg * 64;
        #pragma unroll
        for (int kt = 0; kt < 8; ++kt) {
            Breg[s][kt][0] = tf32u(wrow[kt * 8 + tig]);
            Breg[s][kt][1] = tf32u(wrow[kt * 8 + tig + 4]);
        }
    }
    if (tid < 128) {
        int gate = tid >> 5, jj = tid & 31;
        int grow = gate * HID + j0 + jj;
        BiasS[tid] = b_ih[grow] + b_hh[grow];
        WihS[tid * 4 + 0] = W_ih[grow * IND + 0];
        WihS[tid * 4 + 1] = W_ih[grow * IND + 1];
        WihS[tid * 4 + 2] = W_ih[grow * IND + 2];
        WihS[tid * 4 + 3] = W_ih[grow * IND + 3];
    }
    // zero phase-0 A buffers of both groups (h_0 = 0)
    for (int i = tid; i < AS_BUF; i += THREADS) {
        As[i] = 0.0f;                 // group 0, phase 0
        As[3 * AS_BUF + i] = 0.0f;    // group 1, phase 0
    }
    if (tid < MG)
        *(float4*)(Xs + tid * 4) = *(const float4*)(x + (size_t)(bbase + tid) * SEQ * IND);
    if (tid == 0) {
        #pragma unroll
        for (int i = 0; i < 6; ++i) {           // full[g][ph]
            mbar_init(sbase + i * 8, 1);
            mbar_expect(sbase + i * 8, FULL_TX);
        }
        asm volatile("fence.mbarrier_init.release.cluster;" ::: "memory");
    }
    __syncthreads();
    asm volatile("barrier.cluster.arrive.aligned;" ::: "memory");
    asm volatile("barrier.cluster.wait.aligned;"   ::: "memory");

    // gate-phase ownership: one (row, j) per thread:
    // jl = tid&31, qh = tid>>5 in 0..15 -> group row qh, column j0+jl.
    const int jl = tid & 31;
    const int qh = tid >> 5;
    const int il = (qh < 8) ? (2 * qh) : (2 * (qh - 8) + 1);  // interleave pos

    // hoisted loop-invariant gate weights/biases
    const float4 wiv = *(const float4*)(WihS + (jl)      * 4);
    const float4 wfv = *(const float4*)(WihS + (32 + jl) * 4);
    const float4 wgv = *(const float4*)(WihS + (64 + jl) * 4);
    const float4 wov = *(const float4*)(WihS + (96 + jl) * 4);
    const float bi = BiasS[jl], bf = BiasS[32 + jl];
    const float bg = BiasS[64 + jl], bo = BiasS[96 + jl];

    float cst[2] = {0.f, 0.f};
    uint32_t pf[2][3] = {{0, 0, 0}, {0, 0, 0}};

    int ph = 0;   // t % 3
    for (int t = 0; t < SEQ; ++t) {
        const int p   = t & 1;               // Xs parity only
        const int ph1 = (ph == 2) ? 0 : ph + 1;

        // prefetch x_{t+1}
        float4 xpre;
        const bool do_x = (tid < MG) && (t + 1 < SEQ);
        if (do_x)
            xpre = *(const float4*)(x + ((size_t)(bbase + tid) * SEQ + (t + 1)) * IND);

        #pragma unroll
        for (int gam = 0; gam < 2; ++gam) {
            const uint32_t mbfull_p = sbase + (gam * 3 + ph) * 8;
            const uint32_t mbfull_n = sbase + (gam * 3 + ph1) * 8;

            // wait for this group's A phase (t=0: locally zeroed)
            if (t > 0) {
                mbar_wait(mbfull_p, pf[gam][ph]);
                pf[gam][ph] ^= 1;
                if (tid == 0) mbar_expect(mbfull_p, FULL_TX);
            }

            // ---- z_partial(kg quarter) = h @ W^T for warp's 32 n-rows ----
            const uint32_t* Au = (const uint32_t*)(As + (gam * 3 + ph) * AS_BUF);
            float acc[4][4];
            #pragma unroll
            for (int s = 0; s < 4; ++s)
                #pragma unroll
                for (int q = 0; q < 4; ++q) acc[s][q] = 0.0f;

            #pragma unroll
            for (int kt = 0; kt < 8; ++kt) {
                const int kb = kg * 64 + kt * 8 + tig;
                uint2 A0  = *(const uint2*)(Au + (size_t)kb * AS_KSTR + 2 * g);
                uint2 A0b = *(const uint2*)(Au + (size_t)(kb + 4) * AS_KSTR + 2 * g);
                #pragma unroll
                for (int s = 0; s < 4; ++s) {
                    asm("mma.sync.aligned.m16n8k8.row.col.f32.tf32.tf32.f32 "
                        "{%0,%1,%2,%3},{%4,%5,%6,%7},{%8,%9},{%0,%1,%2,%3};"
                        : "+f"(acc[s][0]), "+f"(acc[s][1]), "+f"(acc[s][2]), "+f"(acc[s][3])
                        : "r"(A0.x), "r"(A0.y), "r"(A0b.x), "r"(A0b.y),
                          "r"(Breg[s][kt][0]), "r"(Breg[s][kt][1]));
                }
            }
            {
                float* Zp = Zs + kg * ZS_BUF;
                #pragma unroll
                for (int s = 0; s < 4; ++s) {
                    const int n0 = nq * 32 + s * 8;
                    *(float2*)(Zp + (size_t)g * ZS_RSTR + n0 + 2 * tig) =
                        make_float2(acc[s][0], acc[s][1]);
                    *(float2*)(Zp + (size_t)(g + 8) * ZS_RSTR + n0 + 2 * tig) =
                        make_float2(acc[s][2], acc[s][3]);
                }
            }
            __syncthreads();   // Z complete (true all-warp dependency)

            // stash prefetched x once per step (covered by later syncs)
            if (gam == 0 && do_x)
                *(float4*)(Xs + (p ^ 1) * (MG * 4) + tid * 4) = xpre;

            // ---- gates: ONE (row qh, col j0+jl) per thread ----
            float hv;
            {
                const int r0 = gam * MGG + qh;
                const float4 xv = *(const float4*)(Xs + p * (MG * 4) + r0 * 4);
                const float* z0 = Zs + (size_t)qh * ZS_RSTR;
                const float* z1 = z0 + ZS_BUF;
                const float* z2 = z1 + ZS_BUF;
                const float* z3 = z2 + ZS_BUF;
                const float ai = ((z0[jl]      + z1[jl])      + (z2[jl]      + z3[jl]))
                                 + bi + dot4(wiv, xv);
                const float af = ((z0[32 + jl] + z1[32 + jl]) + (z2[32 + jl] + z3[32 + jl]))
                                 + bf + dot4(wfv, xv);
                const float ag = ((z0[64 + jl] + z1[64 + jl]) + (z2[64 + jl] + z3[64 + jl]))
                                 + bg + dot4(wgv, xv);
                const float ao = ((z0[96 + jl] + z1[96 + jl]) + (z2[96 + jl] + z3[96 + jl]))
                                 + bo + dot4(wov, xv);
                const float gi = sig_t(ai), gf = sig_t(af), go = sig_t(ao);
                const float gg = tanh_a(ag);
                const float cn = gf * cst[gam] + gi * gg;
                cst[gam] = cn;
                hv = rtf32(go * tanh_a(cn));
            }

            if (t + 1 < SEQ) {
                // publish own value to L2 staging (interleaved A layout)
                __stcg(&g_hx[cid][gam][ph1]
                           [(size_t)rank * SLICE_W + jl * AS_KSTR + il], hv);
                __syncthreads();   // all slice STGs issued before elected fence

                // elected: ONE multicast bulk to all 8 CTAs' A[gam][ph1].
                // Triple buffering: passing full[gam][ph] transitively proves
                // every peer finished reading ph1 (step t-2).
                if (tid == 0) {
                    asm volatile("fence.proxy.async.global;" ::: "memory");
                    const uint32_t dstl =
                        sbase + (OFF_AS + (gam * 3 + ph1) * AS_BUF + j0 * AS_KSTR) * 4;
                    bulk_mc_g2s(dstl, &g_hx[cid][gam][ph1][(size_t)rank * SLICE_W],
                                SLICE_B, mbfull_n, (uint16_t)0xFF);
                }
            } else {
                g_hfin[(size_t)(bbase + gam * MGG + qh) * HID + j0 + jl] = hv;
            }
        }
        ph = ph1;
    }

    // no publish at t=SEQ-1 -> nothing in flight beyond barriers we consumed
    asm volatile("barrier.cluster.arrive.aligned;" ::: "memory");
    asm volatile("barrier.cluster.wait.aligned;"   ::: "memory");
}

// ---------------------------------------------------------------------------
// Kernel 3: head
// ---------------------------------------------------------------------------
__global__ void head_kernel(const float* __restrict__ fc_w,
                            const float* __restrict__ fc_b,
                            const float* __restrict__ out_w,
                            const float* __restrict__ out_b,
                            float* __restrict__ out) {
    __shared__ float hsh[HID];
    __shared__ float r0[256];
    __shared__ float r1[256];
    int b = blockIdx.x, tid = threadIdx.x;
    hsh[tid] = g_hfin[b * HID + tid];
    __syncthreads();
    float cf = g_feat[b], ks = g_feat[BATCH + b];
    const float* wr = fc_w + (size_t)tid * (HID + 2);
    float acc = fc_b[tid] + wr[0] * cf + wr[HID + 1] * ks;
    #pragma unroll 8
    for (int k = 0; k < HID; ++k) acc += wr[1 + k] * hsh[k];
    float hid = fmaxf(acc, 0.0f);
    r0[tid] = hid * out_w[tid];
    r1[tid] = hid * out_w[HID + tid];
    __syncthreads();
    for (int o = 128; o > 0; o >>= 1) {
        if (tid < o) { r0[tid] += r0[tid + o]; r1[tid] += r1[tid + o]; }
        __syncthreads();
    }
    if (tid == 0) {
        float l0 = r0[0] + out_b[0];
        float l1 = r1[0] + out_b[1];
        float m  = fmaxf(l0, l1);
        float e0 = __expf(l0 - m), e1 = __expf(l1 - m);
        float inv = __fdividef(1.0f, e0 + e1);
        out[b * 2 + 0] = e0 * inv;
        out[b * 2 + 1] = e1 * inv;
    }
}

// ---------------------------------------------------------------------------
// launch (lstm first so the fixed ncu sampling slot captures it)
// ---------------------------------------------------------------------------
extern "C" void kernel_launch(void* const* d_in, const int* in_sizes, int n_in,
                              void* d_out, int out_size) {
    const float* x      = (const float*)d_in[0];
    const float* conv_w = (const float*)d_in[1];
    const float* conv_b = (const float*)d_in[2];
    const float* W_ih   = (const float*)d_in[3];
    const float* W_hh   = (const float*)d_in[4];
    const float* b_ih   = (const float*)d_in[5];
    const float* b_hh   = (const float*)d_in[6];
    const float* fc_w   = (const float*)d_in[7];
    const float* fc_b   = (const float*)d_in[8];
    const float* out_w  = (const float*)d_in[9];
    const float* out_b  = (const float*)d_in[10];
    float* out = (float*)d_out;

    cudaFuncSetAttribute(lstm_kernel, cudaFuncAttributeMaxDynamicSharedMemorySize,
                         SMEM_BYTES);

    lstm_kernel<<<NCLUST * CLUSTER, THREADS, SMEM_BYTES>>>(x, W_ih, W_hh, b_ih, b_hh);
    feat_kernel<<<BATCH, 256>>>(x, conv_w, conv_b);
    head_kernel<<<BATCH, 256>>>(fc_w, fc_b, out_w, out_b, out);
}

// round 17
// speedup vs baseline: 1.4477x; 1.3310x over previous
#include <cuda_runtime.h>
#include <cstdint>

// ---------------------------------------------------------------------------
// Problem constants
// ---------------------------------------------------------------------------
#define BATCH  256
#define SEQ    2048
#define IND    4
#define HID    256

// 8 clusters x 8 CTAs = 64 CTAs (single wave).
// Cluster owns 32 batch rows in TWO pipelined groups of 16. CTA rank r owns
// h-indices [32r,32r+32) -> 128 W_hh rows as tf32 register fragments.
// 8 warps: warp = (kg in {0,1}, nq in {0..3}).
// Exchange: STG slice -> L2, ONE cp.async.bulk multicast::cluster per CTA per
// group delivers into all 8 CTAs' A buffers. A is TRIPLE-buffered per group;
// the full-barrier chain replaces any consume barrier (R9 protocol).
// ONLY change vs the 4274us champion: AS_KSTR 20 -> 24. Bank math: A-read
// word addr = tig*S + 2g; S=20 gives tig-offsets {0,20,8,28} whose even-bank
// windows collide pairwise (2-way conflict on every A LDS.64); S=24 gives
// {0,24,16,8} which exactly tile the even banks in both half-warp phases.
#define CLUSTER 8
#define NCLUST  8
#define MG      32
#define MGG     16
#define JPC     32
#define THREADS 256

#define AS_KSTR 24                      // 16 rows + 8 pad; conflict-free LDS.64
#define AS_BUF  (HID * AS_KSTR)         // 6144 floats per buffer
#define ZS_RSTR 132
#define ZS_BUF  (MGG * ZS_RSTR)         // 2112 floats per k-group
#define SLICE_W (JPC * AS_KSTR)         // 768 words per CTA slice
#define SLICE_B (SLICE_W * 4)           // 3072 bytes
#define FULL_TX (CLUSTER * SLICE_B)     // 24576 bytes (8 multicast slices)

// dynamic smem layout (float offsets)
// mbarriers: full[g][ph] at (g*3+ph)*8 bytes (6 barriers, 48 B)
#define OFF_AS    16
#define OFF_ZS    (OFF_AS + 6 * AS_BUF)      // 36880 (A[g][ph] = (g*3+ph)*AS_BUF)
#define OFF_WIH   (OFF_ZS + 2 * ZS_BUF)      // 41104
#define OFF_BIAS  (OFF_WIH + 512)            // 41616
#define OFF_XS    (OFF_BIAS + 128)           // 41744
#define SMEM_FLOATS (OFF_XS + 2 * MG * 4)    // 42000
#define SMEM_BYTES  (SMEM_FLOATS * 4)        // 168000

// ---------------------------------------------------------------------------
// Global scratch
// ---------------------------------------------------------------------------
__device__ float g_hx[NCLUST][2][3][CLUSTER * SLICE_W];  // [clust][group][phase]
__device__ float g_hfin[BATCH * HID];
__device__ float g_feat[2 * BATCH];

// ---------------------------------------------------------------------------
// helpers
// ---------------------------------------------------------------------------
__device__ __forceinline__ uint32_t tf32u(float v) {
    uint32_t r; asm("cvt.rna.tf32.f32 %0, %1;" : "=r"(r) : "f"(v)); return r;
}
__device__ __forceinline__ float rtf32(float v) { return __uint_as_float(tf32u(v)); }
__device__ __forceinline__ float tanh_a(float x) {
    float y; asm("tanh.approx.f32 %0, %1;" : "=f"(y) : "f"(x)); return y;
}
__device__ __forceinline__ float sig_t(float x) { return 0.5f * tanh_a(0.5f * x) + 0.5f; }
__device__ __forceinline__ float fast_sigmoid(float x) {
    float e = __expf(-x); return __fdividef(1.0f, 1.0f + e);
}
__device__ __forceinline__ float dot4(float4 a, float4 b) {
    return a.x * b.x + a.y * b.y + a.z * b.z + a.w * b.w;
}
__device__ __forceinline__ uint32_t smem_u32(const void* p) {
    uint32_t a;
    asm("{ .reg .u64 t; cvta.to.shared.u64 t, %1; cvt.u32.u64 %0, t; }" : "=r"(a) : "l"(p));
    return a;
}
__device__ __forceinline__ uint32_t cta_rank() {
    uint32_t r; asm("mov.u32 %0, %%cluster_ctarank;" : "=r"(r)); return r;
}
__device__ __forceinline__ void mbar_init(uint32_t mbar, uint32_t cnt) {
    asm volatile("mbarrier.init.shared.b64 [%0], %1;" :: "r"(mbar), "r"(cnt) : "memory");
}
__device__ __forceinline__ void mbar_expect(uint32_t mbar, uint32_t bytes) {
    asm volatile("mbarrier.arrive.expect_tx.shared.b64 _, [%0], %1;"
                 :: "r"(mbar), "r"(bytes) : "memory");
}
__device__ __forceinline__ void mbar_wait(uint32_t mbar, uint32_t parity) {
    asm volatile(
        "{\n\t.reg .pred P;\n\t"
        "W_%=:\n\t"
        "mbarrier.try_wait.parity.acquire.cta.shared::cta.b64 P, [%0], %1, 0x989680;\n\t"
        "@P bra D_%=;\n\t"
        "bra W_%=;\n\t"
        "D_%=:\n\t}"
        :: "r"(mbar), "r"(parity) : "memory");
}
__device__ __forceinline__ void bulk_mc_g2s(uint32_t dst, const void* src,
                                            uint32_t bytes, uint32_t mbar,
                                            uint16_t mask) {
    asm volatile("cp.async.bulk.shared::cluster.global."
                 "mbarrier::complete_tx::bytes.multicast::cluster "
                 "[%0], [%1], %2, [%3], %4;"
                 :: "r"(dst), "l"(src), "r"(bytes), "r"(mbar), "h"(mask) : "memory");
}

// ---------------------------------------------------------------------------
// Kernel 1: conv_feat + kernel_sim
// ---------------------------------------------------------------------------
__global__ void feat_kernel(const float* __restrict__ x,
                            const float* __restrict__ conv_w,
                            const float* __restrict__ conv_b) {
    __shared__ float r0[256];
    __shared__ float r1[256];
    int b = blockIdx.x, tid = threadIdx.x;
    float4 cw = *(const float4*)conv_w;
    float cb = conv_b[0];
    const float4* xr = (const float4*)(x + (size_t)b * SEQ * IND);
    float ssig = 0.f, ssq = 0.f;
    for (int s = tid; s < SEQ; s += 256) {
        float4 v = xr[s];
        float d = v.x * cw.x + v.y * cw.y + v.z * cw.z + v.w * cw.w + cb;
        ssig += fast_sigmoid(d);
        ssq  += v.x * v.x + v.y * v.y + v.z * v.z + v.w * v.w;
    }
    r0[tid] = ssig; r1[tid] = ssq;
    __syncthreads();
    for (int o = 128; o > 0; o >>= 1) {
        if (tid < o) { r0[tid] += r0[tid + o]; r1[tid] += r1[tid + o]; }
        __syncthreads();
    }
    if (tid == 0) {
        g_feat[b]         = r0[0] * (1.0f / SEQ);
        g_feat[BATCH + b] = __expf(-r1[0]);
    }
}

// ---------------------------------------------------------------------------
// Kernel 2: LSTM recurrence; R9 protocol, conflict-free A stride
// ---------------------------------------------------------------------------
__global__ void __cluster_dims__(CLUSTER, 1, 1) __launch_bounds__(THREADS, 1)
lstm_kernel(const float* __restrict__ x,
            const float* __restrict__ W_ih,
            const float* __restrict__ W_hh,
            const float* __restrict__ b_ih,
            const float* __restrict__ b_hh) {
    extern __shared__ float sm[];
    float* As    = sm + OFF_AS;
    float* Zs    = sm + OFF_ZS;
    float* WihS  = sm + OFF_WIH;
    float* BiasS = sm + OFF_BIAS;
    float* Xs    = sm + OFF_XS;

    const uint32_t sbase = smem_u32(sm);

    const int tid   = threadIdx.x;
    const int cid   = blockIdx.x / CLUSTER;
    const uint32_t rank = cta_rank();
    const int bbase = cid * MG;
    const int j0    = (int)rank * JPC;
    const int warp  = tid >> 5, lane = tid & 31;
    const int kg    = warp >> 2, nq = warp & 3;
    const int g     = lane >> 2, tig = lane & 3;

    // ---- one-time: W_hh register fragments (tf32) ----
    uint32_t Breg[4][16][2];
    #pragma unroll
    for (int s = 0; s < 4; ++s) {
        const int nl   = nq * 32 + s * 8 + g;
        const int gate = nl >> 5, jj = nl & 31;
        const float* wrow = W_hh + (size_t)(gate * HID + j0 + jj) * HID + kg * 128;
        #pragma unroll
        for (int kt = 0; kt < 16; ++kt) {
            Breg[s][kt][0] = tf32u(wrow[kt * 8 + tig]);
            Breg[s][kt][1] = tf32u(wrow[kt * 8 + tig + 4]);
        }
    }
    if (tid < 128) {
        int gate = tid >> 5, jj = tid & 31;
        int grow = gate * HID + j0 + jj;
        BiasS[tid] = b_ih[grow] + b_hh[grow];
        WihS[tid * 4 + 0] = W_ih[grow * IND + 0];
        WihS[tid * 4 + 1] = W_ih[grow * IND + 1];
        WihS[tid * 4 + 2] = W_ih[grow * IND + 2];
        WihS[tid * 4 + 3] = W_ih[grow * IND + 3];
    }
    // zero phase-0 A buffers of both groups (h_0 = 0)
    for (int i = tid; i < AS_BUF; i += THREADS) {
        As[i] = 0.0f;                 // group 0, phase 0
        As[3 * AS_BUF + i] = 0.0f;    // group 1, phase 0
    }
    if (tid < MG)
        *(float4*)(Xs + tid * 4) = *(const float4*)(x + (size_t)(bbase + tid) * SEQ * IND);
    if (tid == 0) {
        #pragma unroll
        for (int i = 0; i < 6; ++i) {           // full[g][ph]
            mbar_init(sbase + i * 8, 1);
            mbar_expect(sbase + i * 8, FULL_TX);
        }
        asm volatile("fence.mbarrier_init.release.cluster;" ::: "memory");
    }
    __syncthreads();
    asm volatile("barrier.cluster.arrive.aligned;" ::: "memory");
    asm volatile("barrier.cluster.wait.aligned;"   ::: "memory");

    // gate-phase ownership: col jl = tid&31; thread qh = tid>>5 owns group rows
    // {qh, qh+8}  (interleave positions 2qh, 2qh+1)
    const int jl = tid & 31;
    const int qh = tid >> 5;

    // hoisted loop-invariant gate weights/biases
    const float4 wiv = *(const float4*)(WihS + (jl)      * 4);
    const float4 wfv = *(const float4*)(WihS + (32 + jl) * 4);
    const float4 wgv = *(const float4*)(WihS + (64 + jl) * 4);
    const float4 wov = *(const float4*)(WihS + (96 + jl) * 4);
    const float bi = BiasS[jl], bf = BiasS[32 + jl];
    const float bg = BiasS[64 + jl], bo = BiasS[96 + jl];

    float cst[2][2] = {{0.f, 0.f}, {0.f, 0.f}};
    uint32_t pf[2][3] = {{0, 0, 0}, {0, 0, 0}};

    int ph = 0;   // t % 3
    for (int t = 0; t < SEQ; ++t) {
        const int p   = t & 1;               // Xs parity only
        const int ph1 = (ph == 2) ? 0 : ph + 1;

        // prefetch x_{t+1}
        float4 xpre;
        const bool do_x = (tid < MG) && (t + 1 < SEQ);
        if (do_x)
            xpre = *(const float4*)(x + ((size_t)(bbase + tid) * SEQ + (t + 1)) * IND);

        #pragma unroll
        for (int gam = 0; gam < 2; ++gam) {
            const uint32_t mbfull_p = sbase + (gam * 3 + ph) * 8;
            const uint32_t mbfull_n = sbase + (gam * 3 + ph1) * 8;

            // wait for this group's A phase (t=0: locally zeroed)
            if (t > 0) {
                mbar_wait(mbfull_p, pf[gam][ph]);
                pf[gam][ph] ^= 1;
                if (tid == 0) mbar_expect(mbfull_p, FULL_TX);
            }

            // ---- z_partial(kg) = h @ W^T for this warp's 32 n-rows ----
            const uint32_t* Au = (const uint32_t*)(As + (gam * 3 + ph) * AS_BUF);
            float acc[4][4];
            #pragma unroll
            for (int s = 0; s < 4; ++s)
                #pragma unroll
                for (int q = 0; q < 4; ++q) acc[s][q] = 0.0f;

            #pragma unroll
            for (int kt = 0; kt < 16; ++kt) {
                const int kb = kg * 128 + kt * 8 + tig;
                uint2 A0  = *(const uint2*)(Au + (size_t)kb * AS_KSTR + 2 * g);
                uint2 A0b = *(const uint2*)(Au + (size_t)(kb + 4) * AS_KSTR + 2 * g);
                #pragma unroll
                for (int s = 0; s < 4; ++s) {
                    asm("mma.sync.aligned.m16n8k8.row.col.f32.tf32.tf32.f32 "
                        "{%0,%1,%2,%3},{%4,%5,%6,%7},{%8,%9},{%0,%1,%2,%3};"
                        : "+f"(acc[s][0]), "+f"(acc[s][1]), "+f"(acc[s][2]), "+f"(acc[s][3])
                        : "r"(A0.x), "r"(A0.y), "r"(A0b.x), "r"(A0b.y),
                          "r"(Breg[s][kt][0]), "r"(Breg[s][kt][1]));
                }
            }
            {
                float* Zp = Zs + kg * ZS_BUF;
                #pragma unroll
                for (int s = 0; s < 4; ++s) {
                    const int n0 = nq * 32 + s * 8;
                    *(float2*)(Zp + (size_t)g * ZS_RSTR + n0 + 2 * tig) =
                        make_float2(acc[s][0], acc[s][1]);
                    *(float2*)(Zp + (size_t)(g + 8) * ZS_RSTR + n0 + 2 * tig) =
                        make_float2(acc[s][2], acc[s][3]);
                }
            }
            __syncthreads();

            // stash prefetched x once per step (covered by later syncs)
            if (gam == 0 && do_x)
                *(float4*)(Xs + (p ^ 1) * (MG * 4) + tid * 4) = xpre;

            // ---- gates: rows {gam*16+qh, gam*16+qh+8}, column j0+jl ----
            float h0, h1;
            {
                const int r0 = gam * MGG + qh;
                const float4 xv0 = *(const float4*)(Xs + p * (MG * 4) + r0 * 4);
                const float4 xv1 = *(const float4*)(Xs + p * (MG * 4) + (r0 + 8) * 4);
                const float* z0 = Zs + (size_t)qh * ZS_RSTR;        // kg 0
                const float* z1 = z0 + ZS_BUF;                      // kg 1
                const float* y0 = Zs + (size_t)(qh + 8) * ZS_RSTR;
                const float* y1 = y0 + ZS_BUF;
                float ai = z0[jl]      + z1[jl]      + bi + dot4(wiv, xv0);
                float af = z0[32 + jl] + z1[32 + jl] + bf + dot4(wfv, xv0);
                float ag = z0[64 + jl] + z1[64 + jl] + bg + dot4(wgv, xv0);
                float ao = z0[96 + jl] + z1[96 + jl] + bo + dot4(wov, xv0);
                float gi = sig_t(ai), gf = sig_t(af), go = sig_t(ao);
                float gg = tanh_a(ag);
                float cn = gf * cst[gam][0] + gi * gg;
                cst[gam][0] = cn;
                h0 = rtf32(go * tanh_a(cn));

                ai = y0[jl]      + y1[jl]      + bi + dot4(wiv, xv1);
                af = y0[32 + jl] + y1[32 + jl] + bf + dot4(wfv, xv1);
                ag = y0[64 + jl] + y1[64 + jl] + bg + dot4(wgv, xv1);
                ao = y0[96 + jl] + y1[96 + jl] + bo + dot4(wov, xv1);
                gi = sig_t(ai); gf = sig_t(af); go = sig_t(ao);
                gg = tanh_a(ag);
                cn = gf * cst[gam][1] + gi * gg;
                cst[gam][1] = cn;
                h1 = rtf32(go * tanh_a(cn));
            }

            if (t + 1 < SEQ) {
                // publish own slice to L2 staging (interleaved A layout)
                __stcg((float2*)&g_hx[cid][gam][ph1]
                           [(size_t)rank * SLICE_W + jl * AS_KSTR + 2 * qh],
                       make_float2(h0, h1));
                __syncthreads();   // all slice STGs issued before elected fence

                // elected: ONE multicast bulk to all 8 CTAs' A[gam][ph1].
                // Triple buffering: passing full[gam][ph] transitively proves
                // every peer finished reading ph1 (step t-2).
                if (tid == 0) {
                    asm volatile("fence.proxy.async.global;" ::: "memory");
                    const uint32_t dstl =
                        sbase + (OFF_AS + (gam * 3 + ph1) * AS_BUF + j0 * AS_KSTR) * 4;
                    bulk_mc_g2s(dstl, &g_hx[cid][gam][ph1][(size_t)rank * SLICE_W],
                                SLICE_B, mbfull_n, (uint16_t)0xFF);
                }
            } else {
                g_hfin[(size_t)(bbase + gam * MGG + qh) * HID + j0 + jl]     = h0;
                g_hfin[(size_t)(bbase + gam * MGG + qh + 8) * HID + j0 + jl] = h1;
            }
        }
        ph = ph1;
    }

    // no publish at t=SEQ-1 -> nothing in flight beyond barriers we consumed
    asm volatile("barrier.cluster.arrive.aligned;" ::: "memory");
    asm volatile("barrier.cluster.wait.aligned;"   ::: "memory");
}

// ---------------------------------------------------------------------------
// Kernel 3: head
// ---------------------------------------------------------------------------
__global__ void head_kernel(const float* __restrict__ fc_w,
                            const float* __restrict__ fc_b,
                            const float* __restrict__ out_w,
                            const float* __restrict__ out_b,
                            float* __restrict__ out) {
    __shared__ float hsh[HID];
    __shared__ float r0[256];
    __shared__ float r1[256];
    int b = blockIdx.x, tid = threadIdx.x;
    hsh[tid] = g_hfin[b * HID + tid];
    __syncthreads();
    float cf = g_feat[b], ks = g_feat[BATCH + b];
    const float* wr = fc_w + (size_t)tid * (HID + 2);
    float acc = fc_b[tid] + wr[0] * cf + wr[HID + 1] * ks;
    #pragma unroll 8
    for (int k = 0; k < HID; ++k) acc += wr[1 + k] * hsh[k];
    float hid = fmaxf(acc, 0.0f);
    r0[tid] = hid * out_w[tid];
    r1[tid] = hid * out_w[HID + tid];
    __syncthreads();
    for (int o = 128; o > 0; o >>= 1) {
        if (tid < o) { r0[tid] += r0[tid + o]; r1[tid] += r1[tid + o]; }
        __syncthreads();
    }
    if (tid == 0) {
        float l0 = r0[0] + out_b[0];
        float l1 = r1[0] + out_b[1];
        float m  = fmaxf(l0, l1);
        float e0 = __expf(l0 - m), e1 = __expf(l1 - m);
        float inv = __fdividef(1.0f, e0 + e1);
        out[b * 2 + 0] = e0 * inv;
        out[b * 2 + 1] = e1 * inv;
    }
}

// ---------------------------------------------------------------------------
// launch (lstm first so the fixed ncu sampling slot captures it)
// ---------------------------------------------------------------------------
extern "C" void kernel_launch(void* const* d_in, const int* in_sizes, int n_in,
                              void* d_out, int out_size) {
    const float* x      = (const float*)d_in[0];
    const float* conv_w = (const float*)d_in[1];
    const float* conv_b = (const float*)d_in[2];
    const float* W_ih   = (const float*)d_in[3];
    const float* W_hh   = (const float*)d_in[4];
    const float* b_ih   = (const float*)d_in[5];
    const float* b_hh   = (const float*)d_in[6];
    const float* fc_w   = (const float*)d_in[7];
    const float* fc_b   = (const float*)d_in[8];
    const float* out_w  = (const float*)d_in[9];
    const float* out_b  = (const float*)d_in[10];
    float* out = (float*)d_out;

    cudaFuncSetAttribute(lstm_kernel, cudaFuncAttributeMaxDynamicSharedMemorySize,
                         SMEM_BYTES);

    lstm_kernel<<<NCLUST * CLUSTER, THREADS, SMEM_BYTES>>>(x, W_ih, W_hh, b_ih, b_hh);
    feat_kernel<<<BATCH, 256>>>(x, conv_w, conv_b);
    head_kernel<<<BATCH, 256>>>(fc_w, fc_b, out_w, out_b, out);
}